// round 15
// baseline (speedup 1.0000x reference)
#include <cuda_runtime.h>
#include <cuda_bf16.h>
#include <math.h>
#include <cstdint>

// Problem constants
#define B_    16
#define LQ_   64
#define LD_   2048
#define H_    1024
#define DIM_  128
#define KPAD  2112
#define MQ    (B_ * LQ_)      // 1024
#define MD    (B_ * LD_)      // 32768
#define QBLK  (MQ / 128)      // 8
#define DBLK  (MD / 128)      // 256

// -------- scratch --------
__device__ float          g_q_repr[MQ * DIM_];
__device__ float          g_pool  [B_ * KPAD * DIM_];   // segment sums (raw)
__device__ int            g_kb    [B_];
__device__ unsigned int   g_qmax  [B_ * LQ_];
__device__ int            g_tile_cnt[B_];
__device__ __nv_bfloat16  g_Wt    [DIM_ * H_];   // [n][k] bf16

__device__ __forceinline__ unsigned int flipf(float f) {
    unsigned int u = __float_as_uint(f);
    return (u & 0x80000000u) ? ~u : (u | 0x80000000u);
}
__device__ __forceinline__ float unflipf(unsigned int u) {
    return (u & 0x80000000u) ? __uint_as_float(u ^ 0x80000000u)
                             : __uint_as_float(~u);
}
__device__ __forceinline__ uint32_t smem_to_u32(const void* p) {
    uint32_t a;
    asm("{ .reg .u64 t; cvta.to.shared.u64 t, %1; cvt.u32.u64 %0, t; }"
        : "=r"(a) : "l"(p));
    return a;
}
#define CP_ASYNC16(dst, src) \
    asm volatile("cp.async.cg.shared.global [%0], [%1], 16;" \
                 :: "r"((uint32_t)(dst)), "l"(src) : "memory")
#define CP_COMMIT() asm volatile("cp.async.commit_group;" ::: "memory")
#define CP_WAIT0()  asm volatile("cp.async.wait_group 0;" ::: "memory")
#define STS128U(addr, a, b, c, d) \
    asm volatile("st.shared.v4.b32 [%0], {%1,%2,%3,%4};" \
                 :: "r"((uint32_t)(addr)), "r"(a), "r"(b), "r"(c), "r"(d) : "memory")
#define LDSM_X4(r, addr) \
    asm volatile("ldmatrix.sync.aligned.m8n8.x4.shared.b16 {%0,%1,%2,%3}, [%4];" \
                 : "=r"((r)[0]), "=r"((r)[1]), "=r"((r)[2]), "=r"((r)[3]) \
                 : "r"((uint32_t)(addr)))
#define MMA16816(cc, a, b0, b1) \
    asm volatile( \
        "mma.sync.aligned.m16n8k16.row.col.f32.bf16.bf16.f32 " \
        "{%0,%1,%2,%3}, {%4,%5,%6,%7}, {%8,%9}, {%0,%1,%2,%3};" \
        : "+f"((cc)[0]), "+f"((cc)[1]), "+f"((cc)[2]), "+f"((cc)[3]) \
        : "r"((a)[0]), "r"((a)[1]), "r"((a)[2]), "r"((a)[3]), \
          "r"(b0), "r"(b1))

// ======================= kb: per-batch cluster count =======================
__global__ void kb_kernel(const int* __restrict__ d_mask,
                          const int* __restrict__ pf) {
    const int b = blockIdx.x;
    const int tid = threadIdx.x;
    int s = 0;
    for (int i = tid; i < LD_; i += 256)
        s += (d_mask[b * LD_ + i] > 0) ? 1 : 0;
    __shared__ int sm[8];
    for (int o = 16; o; o >>= 1) s += __shfl_down_sync(0xffffffffu, s, o);
    if ((tid & 31) == 0) sm[tid >> 5] = s;
    __syncthreads();
    if (tid == 0) {
        int t = 0;
        #pragma unroll
        for (int w = 0; w < 8; w++) t += sm[w];
        if (t < 2) t = 2;
        int p = pf[0]; if (p < 1) p = 1;
        int k = t / p + 1;
        if (k > KPAD) k = KPAD;
        g_kb[b] = k;
    }
}

// ======================= prep: adaptive pool zero + W transpose + inits ====
#define ZBLK (KPAD / 8)        // 264 blocks per batch
#define NZ   (B_ * ZBLK)       // 4224
__global__ void prep_kernel(const float* __restrict__ Wm) {
    const int blk = blockIdx.x;
    const int tid = threadIdx.x;
    if (blk < NZ) {
        const int b  = blk / ZBLK;
        const int c0 = (blk % ZBLK) * 8;
        if (c0 >= g_kb[b]) return;
        float4* dst = (float4*)(g_pool + ((size_t)(b * KPAD + c0) << 7));
        dst[tid] = make_float4(0.f, 0.f, 0.f, 0.f);   // 256 thr * 16B = 8 clusters
    } else if (blk < NZ + 128) {
        __shared__ float sm[32][33];
        const int wb = blk - NZ;            // 0..127
        const int kt = wb & 31;             // k tile (32 wide)
        const int nt = wb >> 5;             // n tile (32 wide)
        const int r0 = tid >> 5;            // 0..7
        const int cc = tid & 31;
        #pragma unroll
        for (int j = 0; j < 4; j++) {
            int r = r0 + j * 8;
            sm[r][cc] = Wm[(size_t)(kt * 32 + r) * DIM_ + nt * 32 + cc];
        }
        __syncthreads();
        #pragma unroll
        for (int j = 0; j < 4; j++) {
            int nn = r0 + j * 8;            // local n row
            g_Wt[(size_t)(nt * 32 + nn) * H_ + kt * 32 + cc] =
                __float2bfloat16(sm[cc][nn]);
        }
    } else {
        const int qb = blk - NZ - 128;      // 0..3
        g_qmax[qb * 256 + tid] = flipf(-1e4f);
        if (qb == 0 && tid < B_) g_tile_cnt[tid] = 0;
    }
}

// ======================= fused encode (single bf16 mma, BM=128, BK=32) =======
#define ROWB     80                    // bytes per smem row (32 bf16 + pad)
#define A_ARR_B  (128 * ROWB)          // 10240
#define W_ARR_B  (128 * ROWB)          // 10240
#define STAGE_B  (A_ARR_B + W_ARR_B)   // 20480
#define SMEM_DYN (2 * STAGE_B)         // 40960

__global__ __launch_bounds__(256, 2) void encode_kernel(
        const float* __restrict__ q_hidden,
        const float* __restrict__ d_hidden,
        const float* __restrict__ bias,
        const int*   __restrict__ q_mask,
        const int*   __restrict__ d_mask,
        const int*   __restrict__ labels)
{
    extern __shared__ char smem[];
    __shared__ float red[128][4];
    __shared__ float scales[128];
    __shared__ int   labsm[128];

    const uint32_t sb32 = smem_to_u32(smem);
    const int tid  = threadIdx.x;
    const int warp = tid >> 5;
    const int lane = tid & 31;
    const int g    = lane >> 2;
    const int tg   = lane & 3;
    const int wm   = warp >> 2;     // 0..1 -> rows wm*64
    const int wn   = warp & 3;      // 0..3 -> cols wn*32

    const bool is_q = (blockIdx.x < QBLK);
    const float* A    = is_q ? q_hidden : d_hidden;
    const int*   mask = is_q ? q_mask   : d_mask;
    const int    bm   = is_q ? (int)blockIdx.x * 128 : ((int)blockIdx.x - QBLK) * 128;

    float c[4][4][4];
    #pragma unroll
    for (int mt = 0; mt < 4; mt++)
        #pragma unroll
        for (int nt = 0; nt < 4; nt++)
            #pragma unroll
            for (int r = 0; r < 4; r++) c[mt][nt][r] = 0.0f;

    // A-load: 2 threads/row, 16 fp32 each
    const int arow = tid >> 1;
    const int aq   = (tid & 1) * 16;
    const float* aptr = A + (size_t)(bm + arow) * H_ + aq;
    const uint32_t a_sts = (uint32_t)(arow * ROWB + aq * 2);
    // W-load: 2 cp.async chunks per thread
    const int wr0 = tid >> 2;
    const int wq0 = (tid & 3) * 8;
    const int wr1 = (tid + 256) >> 2;
    const int wq1 = ((tid + 256) & 3) * 8;
    const __nv_bfloat16* whp0 = g_Wt + (size_t)wr0 * H_ + wq0;
    const __nv_bfloat16* whp1 = g_Wt + (size_t)wr1 * H_ + wq1;
    const uint32_t w_sts0 = (uint32_t)(wr0 * ROWB + wq0 * 2);
    const uint32_t w_sts1 = (uint32_t)(wr1 * ROWB + wq1 * 2);

    // ldmatrix per-lane offsets
    const uint32_t a_ld = (uint32_t)((wm * 64 + (lane & 15)) * ROWB + (lane >> 4) * 16);
    const uint32_t b_ld = (uint32_t)(((lane & 7) + ((lane >> 4) << 3) + wn * 32) * ROWB
                                     + ((lane >> 3) & 1) * 16);

    const uint32_t st0 = sb32;
    const uint32_t st1 = sb32 + STAGE_B;

    auto put_a = [&](uint32_t stage, const float* av) {
        uint32_t hw[8];
        #pragma unroll
        for (int q = 0; q < 8; q++) {
            __nv_bfloat162 hp(__float2bfloat16(av[2 * q]),
                              __float2bfloat16(av[2 * q + 1]));
            hw[q] = *(uint32_t*)&hp;
        }
        STS128U(stage + a_sts,      hw[0], hw[1], hw[2], hw[3]);
        STS128U(stage + a_sts + 16, hw[4], hw[5], hw[6], hw[7]);
    };
    auto load_w = [&](uint32_t stage, int k0) {
        const uint32_t wh = stage + A_ARR_B;
        CP_ASYNC16(wh + w_sts0, whp0 + k0);
        CP_ASYNC16(wh + w_sts1, whp1 + k0);
    };

    // ---- preload stage 0 ----
    {
        load_w(st0, 0);
        CP_COMMIT();
        float av[16];
        #pragma unroll
        for (int j = 0; j < 4; j++)
            *(float4*)&av[4 * j] = *(const float4*)(aptr + 4 * j);
        put_a(st0, av);
        CP_WAIT0();
    }
    __syncthreads();

    const int NIT = H_ / 32;   // 32
    for (int it = 0; it < NIT; it++) {
        const uint32_t cb = (it & 1) ? st1 : st0;
        const uint32_t nb = (it & 1) ? st0 : st1;
        float av[16];
        if (it + 1 < NIT) {
            const int ko = (it + 1) * 32;
            load_w(nb, ko);
            CP_COMMIT();
            #pragma unroll
            for (int j = 0; j < 4; j++)
                *(float4*)&av[4 * j] = *(const float4*)(aptr + ko + 4 * j);
        }

        #pragma unroll
        for (int ksub = 0; ksub < 2; ksub++) {
            const uint32_t ko = ksub * 32;     // byte offset within row
            uint32_t af[4][4], bh[8];
            LDSM_X4(af[0], cb + a_ld + ko);
            LDSM_X4(af[1], cb + a_ld + ko + 16 * ROWB);
            LDSM_X4(af[2], cb + a_ld + ko + 32 * ROWB);
            LDSM_X4(af[3], cb + a_ld + ko + 48 * ROWB);
            LDSM_X4(&bh[0], cb + A_ARR_B + b_ld + ko);
            LDSM_X4(&bh[4], cb + A_ARR_B + b_ld + ko + 16 * ROWB);
            #pragma unroll
            for (int mt = 0; mt < 4; mt++)
                #pragma unroll
                for (int nt = 0; nt < 4; nt++)
                    MMA16816(c[mt][nt], af[mt], bh[nt * 2], bh[nt * 2 + 1]);
        }

        if (it + 1 < NIT) {
            put_a(nb, av);
            CP_WAIT0();
        }
        __syncthreads();
    }

    // ---- bias ----
    #pragma unroll
    for (int nt = 0; nt < 4; nt++) {
        int bcol = wn * 32 + nt * 8 + 2 * tg;
        float2 bb = *(const float2*)&bias[bcol];
        #pragma unroll
        for (int mt = 0; mt < 4; mt++) {
            c[mt][nt][0] += bb.x; c[mt][nt][1] += bb.y;
            c[mt][nt][2] += bb.x; c[mt][nt][3] += bb.y;
        }
    }

    // ---- row sum-of-squares ----
    #pragma unroll
    for (int mt = 0; mt < 4; mt++) {
        float slo = 0.0f, shi = 0.0f;
        #pragma unroll
        for (int nt = 0; nt < 4; nt++) {
            slo = fmaf(c[mt][nt][0], c[mt][nt][0], slo);
            slo = fmaf(c[mt][nt][1], c[mt][nt][1], slo);
            shi = fmaf(c[mt][nt][2], c[mt][nt][2], shi);
            shi = fmaf(c[mt][nt][3], c[mt][nt][3], shi);
        }
        slo += __shfl_xor_sync(0xffffffffu, slo, 1);
        slo += __shfl_xor_sync(0xffffffffu, slo, 2);
        shi += __shfl_xor_sync(0xffffffffu, shi, 1);
        shi += __shfl_xor_sync(0xffffffffu, shi, 2);
        if (tg == 0) {
            red[wm * 64 + mt * 16 + g][wn]     = slo;
            red[wm * 64 + mt * 16 + g + 8][wn] = shi;
        }
    }
    __syncthreads();

    if (tid < 128) {
        float tot = red[tid][0] + red[tid][1] + red[tid][2] + red[tid][3];
        float scale = 1.0f / fmaxf(sqrtf(tot), 1e-12f);
        scales[tid] = scale * (float)mask[bm + tid];
        if (!is_q) {
            int r = bm + tid;
            int b = r >> 11;
            labsm[tid] = (b * KPAD + labels[r] % g_kb[b]) * DIM_;
        }
    }
    __syncthreads();

    if (is_q) {
        #pragma unroll
        for (int mt = 0; mt < 4; mt++) {
            int rl = wm * 64 + mt * 16 + g;
            float sl = scales[rl], sh = scales[rl + 8];
            #pragma unroll
            for (int nt = 0; nt < 4; nt++) {
                int col = wn * 32 + nt * 8 + 2 * tg;
                float2 v0 = make_float2(c[mt][nt][0] * sl, c[mt][nt][1] * sl);
                float2 v1 = make_float2(c[mt][nt][2] * sh, c[mt][nt][3] * sh);
                *(float2*)&g_q_repr[(size_t)(bm + rl) * DIM_ + col]     = v0;
                *(float2*)&g_q_repr[(size_t)(bm + rl + 8) * DIM_ + col] = v1;
            }
        }
    } else {
        #pragma unroll
        for (int mt = 0; mt < 4; mt++) {
            int rl = wm * 64 + mt * 16 + g;
            float sl = scales[rl], sh = scales[rl + 8];
            int dl = labsm[rl], dh = labsm[rl + 8];
            #pragma unroll
            for (int nt = 0; nt < 4; nt++) {
                int col = wn * 32 + nt * 8 + 2 * tg;
                atomicAdd(&g_pool[dl + col],     c[mt][nt][0] * sl);
                atomicAdd(&g_pool[dl + col + 1], c[mt][nt][1] * sl);
                atomicAdd(&g_pool[dh + col],     c[mt][nt][2] * sh);
                atomicAdd(&g_pool[dh + col + 1], c[mt][nt][3] * sh);
            }
        }
    }
}

// ======================= score: sim + max + fused final reduction ==========
// grid (KPAD/64, B_), 256 threads, tile 64q x 64k, micro 4q x 4k,
// software-pipelined d-loop. Norm folded into epilogue. Fused final sum.
#define SCQ 68
#define SCK 68
#define SC_SMEM ((128 * SCQ + 128 * SCK) * 4)    // 69632

__global__ __launch_bounds__(256) void score_kernel(
        const int* __restrict__ q_mask, float* __restrict__ out) {
    const int b  = blockIdx.y;
    const int kb = g_kb[b];
    const int k0 = blockIdx.x * 64;
    if (k0 >= kb) return;

    extern __shared__ float ss[];
    float (*qs)[SCQ] = (float(*)[SCQ])ss;                  // [d][q]
    float (*ps)[SCK] = (float(*)[SCK])(ss + 128 * SCQ);    // [d][k]
    __shared__ float red[64][4];
    __shared__ float scl[64];
    __shared__ int   lastflag;

    const int tid = threadIdx.x;

    for (int lin = tid; lin < 64 * 128; lin += 256) {
        int r = lin >> 7, d = lin & 127;
        qs[d][r] = g_q_repr[((size_t)(b * LQ_ + r) << 7) + d];
        ps[d][r] = g_pool  [((size_t)(b * KPAD + k0 + r) << 7) + d];
    }
    __syncthreads();

    // ---- column sum-of-squares of pool clusters ----
    {
        const int col = tid & 63;
        const int qu  = tid >> 6;           // 0..3 -> d range qu*32..+31
        float s = 0.0f;
        #pragma unroll
        for (int d = 0; d < 32; d++) {
            float v = ps[qu * 32 + d][col];
            s = fmaf(v, v, s);
        }
        red[col][qu] = s;
    }
    __syncthreads();
    if (tid < 64) {
        float tot = red[tid][0] + red[tid][1] + red[tid][2] + red[tid][3];
        scl[tid] = 1.0f / fmaxf(sqrtf(tot), 1e-12f);
    }
    __syncthreads();

    // ---- 64x64 sim, 4x4 micro, software-pipelined ----
    const int tq = tid >> 4;   // 0..15
    const int tk = tid & 15;   // 0..15

    float acc[4][4];
    #pragma unroll
    for (int i = 0; i < 4; i++)
        #pragma unroll
        for (int j = 0; j < 4; j++) acc[i][j] = 0.0f;

    float4 qv = *(const float4*)&qs[0][tq * 4];
    float4 pv = *(const float4*)&ps[0][tk * 4];
    #pragma unroll 4
    for (int d = 0; d < 127; d++) {
        float4 qn = *(const float4*)&qs[d + 1][tq * 4];
        float4 pn = *(const float4*)&ps[d + 1][tk * 4];
        float qa[4] = {qv.x, qv.y, qv.z, qv.w};
        float pa[4] = {pv.x, pv.y, pv.z, pv.w};
        #pragma unroll
        for (int i = 0; i < 4; i++)
            #pragma unroll
            for (int j = 0; j < 4; j++)
                acc[i][j] = fmaf(qa[i], pa[j], acc[i][j]);
        qv = qn; pv = pn;
    }
    {
        float qa[4] = {qv.x, qv.y, qv.z, qv.w};
        float pa[4] = {pv.x, pv.y, pv.z, pv.w};
        #pragma unroll
        for (int i = 0; i < 4; i++)
            #pragma unroll
            for (int j = 0; j < 4; j++)
                acc[i][j] = fmaf(qa[i], pa[j], acc[i][j]);
    }

    // ---- per-q max over valid clusters (norm folded: s > 0) ----
    const int kleft = kb - k0;
    float s4[4];
    #pragma unroll
    for (int j = 0; j < 4; j++) s4[j] = scl[tk * 4 + j];
    #pragma unroll
    for (int i = 0; i < 4; i++) {
        float m = -3.4e38f;
        #pragma unroll
        for (int j = 0; j < 4; j++)
            if (tk * 4 + j < kleft) m = fmaxf(m, acc[i][j] * s4[j]);
        #pragma unroll
        for (int o = 1; o < 16; o <<= 1)
            m = fmaxf(m, __shfl_xor_sync(0xffffffffu, m, o));
        if (tk == 0)
            atomicMax(&g_qmax[b * LQ_ + tq * 4 + i], flipf(m));
    }

    // ---- last block for this batch computes the final sum ----
    __syncthreads();
    __threadfence();
    if (tid == 0) {
        int ntiles = (kb + 63) >> 6;
        lastflag = (atomicAdd(&g_tile_cnt[b], 1) == ntiles - 1);
    }
    __syncthreads();
    if (lastflag) {
        if (tid < 64) {
            float v = unflipf(g_qmax[b * LQ_ + tid]) *
                      (float)q_mask[b * LQ_ + tid];
            #pragma unroll
            for (int o = 16; o; o >>= 1)
                v += __shfl_down_sync(0xffffffffu, v, o);
            if ((tid & 31) == 0) red[0][tid >> 5] = v;
        }
        __syncthreads();
        if (tid == 0) out[b] = red[0][0] + red[0][1];
    }
}

// ======================= launch =======================
extern "C" void kernel_launch(void* const* d_in, const int* in_sizes, int n_in,
                              void* d_out, int out_size) {
    const float* q_hidden = (const float*)d_in[0];
    const float* d_hidden = (const float*)d_in[1];
    const float* Wm       = (const float*)d_in[2];
    const float* bias     = (const float*)d_in[3];
    const int*   q_mask   = (const int*)  d_in[4];
    const int*   d_mask   = (const int*)  d_in[5];
    const int*   labels   = (const int*)  d_in[6];
    const int*   pf       = (const int*)  d_in[7];
    float*       out      = (float*)d_out;

    cudaFuncSetAttribute(encode_kernel,
                         cudaFuncAttributeMaxDynamicSharedMemorySize, SMEM_DYN);
    cudaFuncSetAttribute(score_kernel,
                         cudaFuncAttributeMaxDynamicSharedMemorySize, SC_SMEM);

    kb_kernel<<<B_, 256>>>(d_mask, pf);
    prep_kernel<<<NZ + 128 + 4, 256>>>(Wm);
    encode_kernel<<<QBLK + DBLK, 256, SMEM_DYN>>>(q_hidden, d_hidden, bias,
                                                  q_mask, d_mask, labels);
    dim3 sg(KPAD / 64, B_);
    score_kernel<<<sg, 256, SC_SMEM>>>(q_mask, out);
}

// round 16
// speedup vs baseline: 1.0224x; 1.0224x over previous
#include <cuda_runtime.h>
#include <cuda_bf16.h>
#include <math.h>
#include <cstdint>

// Problem constants
#define B_    16
#define LQ_   64
#define LD_   2048
#define H_    1024
#define DIM_  128
#define KPAD  2112
#define MQ    (B_ * LQ_)      // 1024
#define MD    (B_ * LD_)      // 32768
#define QBLK  (MQ / 128)      // 8
#define DBLK  (MD / 128)      // 256

// -------- scratch --------
__device__ float          g_q_repr[MQ * DIM_];
__device__ float          g_pool  [B_ * KPAD * DIM_];   // segment sums (raw)
__device__ int            g_kb    [B_];
__device__ unsigned int   g_qmax  [B_ * LQ_];
__device__ int            g_tile_cnt[B_];
__device__ __nv_bfloat16  g_Wt    [DIM_ * H_];   // [n][k] bf16

__device__ __forceinline__ unsigned int flipf(float f) {
    unsigned int u = __float_as_uint(f);
    return (u & 0x80000000u) ? ~u : (u | 0x80000000u);
}
__device__ __forceinline__ float unflipf(unsigned int u) {
    return (u & 0x80000000u) ? __uint_as_float(u ^ 0x80000000u)
                             : __uint_as_float(~u);
}
__device__ __forceinline__ uint32_t smem_to_u32(const void* p) {
    uint32_t a;
    asm("{ .reg .u64 t; cvta.to.shared.u64 t, %1; cvt.u32.u64 %0, t; }"
        : "=r"(a) : "l"(p));
    return a;
}
#define CP_ASYNC16(dst, src) \
    asm volatile("cp.async.cg.shared.global [%0], [%1], 16;" \
                 :: "r"((uint32_t)(dst)), "l"(src) : "memory")
#define CP_COMMIT() asm volatile("cp.async.commit_group;" ::: "memory")
#define CP_WAIT0()  asm volatile("cp.async.wait_group 0;" ::: "memory")
#define STS128U(addr, a, b, c, d) \
    asm volatile("st.shared.v4.b32 [%0], {%1,%2,%3,%4};" \
                 :: "r"((uint32_t)(addr)), "r"(a), "r"(b), "r"(c), "r"(d) : "memory")
#define LDSM_X4(r, addr) \
    asm volatile("ldmatrix.sync.aligned.m8n8.x4.shared.b16 {%0,%1,%2,%3}, [%4];" \
                 : "=r"((r)[0]), "=r"((r)[1]), "=r"((r)[2]), "=r"((r)[3]) \
                 : "r"((uint32_t)(addr)))
#define MMA16816(cc, a, b0, b1) \
    asm volatile( \
        "mma.sync.aligned.m16n8k16.row.col.f32.bf16.bf16.f32 " \
        "{%0,%1,%2,%3}, {%4,%5,%6,%7}, {%8,%9}, {%0,%1,%2,%3};" \
        : "+f"((cc)[0]), "+f"((cc)[1]), "+f"((cc)[2]), "+f"((cc)[3]) \
        : "r"((a)[0]), "r"((a)[1]), "r"((a)[2]), "r"((a)[3]), \
          "r"(b0), "r"(b1))

// ======================= kb: per-batch cluster count =======================
__global__ void kb_kernel(const int* __restrict__ d_mask,
                          const int* __restrict__ pf) {
    const int b = blockIdx.x;
    const int tid = threadIdx.x;
    int s = 0;
    for (int i = tid; i < LD_; i += 256)
        s += (d_mask[b * LD_ + i] > 0) ? 1 : 0;
    __shared__ int sm[8];
    for (int o = 16; o; o >>= 1) s += __shfl_down_sync(0xffffffffu, s, o);
    if ((tid & 31) == 0) sm[tid >> 5] = s;
    __syncthreads();
    if (tid == 0) {
        int t = 0;
        #pragma unroll
        for (int w = 0; w < 8; w++) t += sm[w];
        if (t < 2) t = 2;
        int p = pf[0]; if (p < 1) p = 1;
        int k = t / p + 1;
        if (k > KPAD) k = KPAD;
        g_kb[b] = k;
    }
}

// ======================= prep: adaptive pool zero + W transpose + inits ====
#define ZBLK (KPAD / 8)        // 264 blocks per batch
#define NZ   (B_ * ZBLK)       // 4224
__global__ void prep_kernel(const float* __restrict__ Wm) {
    const int blk = blockIdx.x;
    const int tid = threadIdx.x;
    if (blk < NZ) {
        const int b  = blk / ZBLK;
        const int c0 = (blk % ZBLK) * 8;
        if (c0 >= g_kb[b]) return;
        float4* dst = (float4*)(g_pool + ((size_t)(b * KPAD + c0) << 7));
        dst[tid] = make_float4(0.f, 0.f, 0.f, 0.f);   // 256 thr * 16B = 8 clusters
    } else if (blk < NZ + 128) {
        __shared__ float sm[32][33];
        const int wb = blk - NZ;            // 0..127
        const int kt = wb & 31;             // k tile (32 wide)
        const int nt = wb >> 5;             // n tile (32 wide)
        const int r0 = tid >> 5;            // 0..7
        const int cc = tid & 31;
        #pragma unroll
        for (int j = 0; j < 4; j++) {
            int r = r0 + j * 8;
            sm[r][cc] = Wm[(size_t)(kt * 32 + r) * DIM_ + nt * 32 + cc];
        }
        __syncthreads();
        #pragma unroll
        for (int j = 0; j < 4; j++) {
            int nn = r0 + j * 8;            // local n row
            g_Wt[(size_t)(nt * 32 + nn) * H_ + kt * 32 + cc] =
                __float2bfloat16(sm[cc][nn]);
        }
    } else {
        const int qb = blk - NZ - 128;      // 0..3
        g_qmax[qb * 256 + tid] = flipf(-1e4f);
        if (qb == 0 && tid < B_) g_tile_cnt[tid] = 0;
    }
}

// ======================= fused encode (single bf16 mma, BM=128, BK=32) =======
#define ROWB     80                    // bytes per smem row (32 bf16 + pad)
#define A_ARR_B  (128 * ROWB)          // 10240
#define W_ARR_B  (128 * ROWB)          // 10240
#define STAGE_B  (A_ARR_B + W_ARR_B)   // 20480
#define SMEM_DYN (2 * STAGE_B)         // 40960

__global__ __launch_bounds__(256, 2) void encode_kernel(
        const float* __restrict__ q_hidden,
        const float* __restrict__ d_hidden,
        const float* __restrict__ bias,
        const int*   __restrict__ q_mask,
        const int*   __restrict__ d_mask,
        const int*   __restrict__ labels)
{
    extern __shared__ char smem[];
    __shared__ float red[128][4];
    __shared__ float scales[128];
    __shared__ int   labsm[128];

    const uint32_t sb32 = smem_to_u32(smem);
    const int tid  = threadIdx.x;
    const int warp = tid >> 5;
    const int lane = tid & 31;
    const int g    = lane >> 2;
    const int tg   = lane & 3;
    const int wm   = warp >> 2;     // 0..1 -> rows wm*64
    const int wn   = warp & 3;      // 0..3 -> cols wn*32

    const bool is_q = (blockIdx.x < QBLK);
    const float* A    = is_q ? q_hidden : d_hidden;
    const int*   mask = is_q ? q_mask   : d_mask;
    const int    bm   = is_q ? (int)blockIdx.x * 128 : ((int)blockIdx.x - QBLK) * 128;

    float c[4][4][4];
    #pragma unroll
    for (int mt = 0; mt < 4; mt++)
        #pragma unroll
        for (int nt = 0; nt < 4; nt++)
            #pragma unroll
            for (int r = 0; r < 4; r++) c[mt][nt][r] = 0.0f;

    // A-load: 2 threads/row, 16 fp32 each
    const int arow = tid >> 1;
    const int aq   = (tid & 1) * 16;
    const float* aptr = A + (size_t)(bm + arow) * H_ + aq;
    const uint32_t a_sts = (uint32_t)(arow * ROWB + aq * 2);
    // W-load: 2 cp.async chunks per thread
    const int wr0 = tid >> 2;
    const int wq0 = (tid & 3) * 8;
    const int wr1 = (tid + 256) >> 2;
    const int wq1 = ((tid + 256) & 3) * 8;
    const __nv_bfloat16* whp0 = g_Wt + (size_t)wr0 * H_ + wq0;
    const __nv_bfloat16* whp1 = g_Wt + (size_t)wr1 * H_ + wq1;
    const uint32_t w_sts0 = (uint32_t)(wr0 * ROWB + wq0 * 2);
    const uint32_t w_sts1 = (uint32_t)(wr1 * ROWB + wq1 * 2);

    // ldmatrix per-lane offsets
    const uint32_t a_ld = (uint32_t)((wm * 64 + (lane & 15)) * ROWB + (lane >> 4) * 16);
    const uint32_t b_ld = (uint32_t)(((lane & 7) + ((lane >> 4) << 3) + wn * 32) * ROWB
                                     + ((lane >> 3) & 1) * 16);

    const uint32_t st0 = sb32;
    const uint32_t st1 = sb32 + STAGE_B;

    auto put_a = [&](uint32_t stage, const float* av) {
        uint32_t hw[8];
        #pragma unroll
        for (int q = 0; q < 8; q++) {
            __nv_bfloat162 hp(__float2bfloat16(av[2 * q]),
                              __float2bfloat16(av[2 * q + 1]));
            hw[q] = *(uint32_t*)&hp;
        }
        STS128U(stage + a_sts,      hw[0], hw[1], hw[2], hw[3]);
        STS128U(stage + a_sts + 16, hw[4], hw[5], hw[6], hw[7]);
    };
    auto load_w = [&](uint32_t stage, int k0) {
        const uint32_t wh = stage + A_ARR_B;
        CP_ASYNC16(wh + w_sts0, whp0 + k0);
        CP_ASYNC16(wh + w_sts1, whp1 + k0);
    };

    // ---- preload stage 0 ----
    {
        load_w(st0, 0);
        CP_COMMIT();
        float av[16];
        #pragma unroll
        for (int j = 0; j < 4; j++)
            *(float4*)&av[4 * j] = *(const float4*)(aptr + 4 * j);
        put_a(st0, av);
        CP_WAIT0();
    }
    __syncthreads();

    const int NIT = H_ / 32;   // 32
    for (int it = 0; it < NIT; it++) {
        const uint32_t cb = (it & 1) ? st1 : st0;
        const uint32_t nb = (it & 1) ? st0 : st1;
        float av[16];
        if (it + 1 < NIT) {
            const int ko = (it + 1) * 32;
            load_w(nb, ko);
            CP_COMMIT();
            #pragma unroll
            for (int j = 0; j < 4; j++)
                *(float4*)&av[4 * j] = *(const float4*)(aptr + ko + 4 * j);
        }

        #pragma unroll
        for (int ksub = 0; ksub < 2; ksub++) {
            const uint32_t ko = ksub * 32;     // byte offset within row
            uint32_t af[4][4], bh[8];
            LDSM_X4(af[0], cb + a_ld + ko);
            LDSM_X4(af[1], cb + a_ld + ko + 16 * ROWB);
            LDSM_X4(af[2], cb + a_ld + ko + 32 * ROWB);
            LDSM_X4(af[3], cb + a_ld + ko + 48 * ROWB);
            LDSM_X4(&bh[0], cb + A_ARR_B + b_ld + ko);
            LDSM_X4(&bh[4], cb + A_ARR_B + b_ld + ko + 16 * ROWB);
            #pragma unroll
            for (int mt = 0; mt < 4; mt++)
                #pragma unroll
                for (int nt = 0; nt < 4; nt++)
                    MMA16816(c[mt][nt], af[mt], bh[nt * 2], bh[nt * 2 + 1]);
        }

        if (it + 1 < NIT) {
            put_a(nb, av);
            CP_WAIT0();
        }
        __syncthreads();
    }

    // ---- bias ----
    #pragma unroll
    for (int nt = 0; nt < 4; nt++) {
        int bcol = wn * 32 + nt * 8 + 2 * tg;
        float2 bb = *(const float2*)&bias[bcol];
        #pragma unroll
        for (int mt = 0; mt < 4; mt++) {
            c[mt][nt][0] += bb.x; c[mt][nt][1] += bb.y;
            c[mt][nt][2] += bb.x; c[mt][nt][3] += bb.y;
        }
    }

    // ---- row sum-of-squares ----
    #pragma unroll
    for (int mt = 0; mt < 4; mt++) {
        float slo = 0.0f, shi = 0.0f;
        #pragma unroll
        for (int nt = 0; nt < 4; nt++) {
            slo = fmaf(c[mt][nt][0], c[mt][nt][0], slo);
            slo = fmaf(c[mt][nt][1], c[mt][nt][1], slo);
            shi = fmaf(c[mt][nt][2], c[mt][nt][2], shi);
            shi = fmaf(c[mt][nt][3], c[mt][nt][3], shi);
        }
        slo += __shfl_xor_sync(0xffffffffu, slo, 1);
        slo += __shfl_xor_sync(0xffffffffu, slo, 2);
        shi += __shfl_xor_sync(0xffffffffu, shi, 1);
        shi += __shfl_xor_sync(0xffffffffu, shi, 2);
        if (tg == 0) {
            red[wm * 64 + mt * 16 + g][wn]     = slo;
            red[wm * 64 + mt * 16 + g + 8][wn] = shi;
        }
    }
    __syncthreads();

    if (tid < 128) {
        float tot = red[tid][0] + red[tid][1] + red[tid][2] + red[tid][3];
        float scale = 1.0f / fmaxf(sqrtf(tot), 1e-12f);
        scales[tid] = scale * (float)mask[bm + tid];
        if (!is_q) {
            int r = bm + tid;
            int b = r >> 11;
            labsm[tid] = (b * KPAD + labels[r] % g_kb[b]) * DIM_;
        }
    }
    __syncthreads();

    if (is_q) {
        #pragma unroll
        for (int mt = 0; mt < 4; mt++) {
            int rl = wm * 64 + mt * 16 + g;
            float sl = scales[rl], sh = scales[rl + 8];
            #pragma unroll
            for (int nt = 0; nt < 4; nt++) {
                int col = wn * 32 + nt * 8 + 2 * tg;
                float2 v0 = make_float2(c[mt][nt][0] * sl, c[mt][nt][1] * sl);
                float2 v1 = make_float2(c[mt][nt][2] * sh, c[mt][nt][3] * sh);
                *(float2*)&g_q_repr[(size_t)(bm + rl) * DIM_ + col]     = v0;
                *(float2*)&g_q_repr[(size_t)(bm + rl + 8) * DIM_ + col] = v1;
            }
        }
    } else {
        #pragma unroll
        for (int mt = 0; mt < 4; mt++) {
            int rl = wm * 64 + mt * 16 + g;
            float sl = scales[rl], sh = scales[rl + 8];
            int dl = labsm[rl], dh = labsm[rl + 8];
            #pragma unroll
            for (int nt = 0; nt < 4; nt++) {
                int col = wn * 32 + nt * 8 + 2 * tg;
                atomicAdd(&g_pool[dl + col],     c[mt][nt][0] * sl);
                atomicAdd(&g_pool[dl + col + 1], c[mt][nt][1] * sl);
                atomicAdd(&g_pool[dh + col],     c[mt][nt][2] * sh);
                atomicAdd(&g_pool[dh + col + 1], c[mt][nt][3] * sh);
            }
        }
    }
}

// ======================= score: 3-split bf16 mma sim + max + fused final ====
// grid (KPAD/64, B_), 256 threads, tile 64q x 64k.
// 8 warps: wm = warp>>1 (q rows wm*16), wn = warp&1 (k cols wn*32).
// Tiles converted fp32 -> hi/lo bf16 in smem; dot = qh*ph + qh*pl + ql*ph.
// Cluster L2-norm folded into epilogue; last block per batch does out[b].
#define SROWB   272                     // 128 bf16 (256 B) + 16 B pad
#define SC_ARR  (64 * SROWB)            // 17408
#define SC_SMEM (4 * SC_ARR)            // 69632

__global__ __launch_bounds__(256) void score_kernel(
        const int* __restrict__ q_mask, float* __restrict__ out) {
    const int b  = blockIdx.y;
    const int kb = g_kb[b];
    const int k0 = blockIdx.x * 64;
    if (k0 >= kb) return;

    extern __shared__ char ss[];
    const uint32_t sb = smem_to_u32(ss);
    const uint32_t qh = sb;
    const uint32_t ql = sb + SC_ARR;
    const uint32_t ph = sb + 2 * SC_ARR;
    const uint32_t pl = sb + 3 * SC_ARR;
    __shared__ float red[64][4];
    __shared__ float scl[64];
    __shared__ int   lastflag;

    const int tid  = threadIdx.x;
    const int lane = tid & 31;
    const int warp = tid >> 5;

    // ---- load + convert: thread owns 32 d of one row for q and one row for p ----
    {
        const int r  = tid >> 2;            // 0..63
        const int dp = (tid & 3) * 32;      // 0,32,64,96
        const float* qsrc = g_q_repr + ((size_t)(b * LQ_ + r) << 7) + dp;
        const float* psrc = g_pool   + ((size_t)(b * KPAD + k0 + r) << 7) + dp;
        const uint32_t sts = (uint32_t)(r * SROWB + dp * 2);
        float ssq = 0.0f;
        #pragma unroll
        for (int j = 0; j < 4; j++) {
            float4 a0 = *(const float4*)(qsrc + j * 8);
            float4 a1 = *(const float4*)(qsrc + j * 8 + 4);
            float av[8] = {a0.x, a0.y, a0.z, a0.w, a1.x, a1.y, a1.z, a1.w};
            uint32_t hw[4], lw[4];
            #pragma unroll
            for (int q = 0; q < 4; q++) {
                __nv_bfloat16 h0 = __float2bfloat16(av[2 * q]);
                __nv_bfloat16 h1 = __float2bfloat16(av[2 * q + 1]);
                __nv_bfloat162 hp(h0, h1);
                __nv_bfloat162 lp(__float2bfloat16(av[2 * q]     - __bfloat162float(h0)),
                                  __float2bfloat16(av[2 * q + 1] - __bfloat162float(h1)));
                hw[q] = *(uint32_t*)&hp;
                lw[q] = *(uint32_t*)&lp;
            }
            STS128U(qh + sts + j * 16, hw[0], hw[1], hw[2], hw[3]);
            STS128U(ql + sts + j * 16, lw[0], lw[1], lw[2], lw[3]);
        }
        #pragma unroll
        for (int j = 0; j < 4; j++) {
            float4 a0 = *(const float4*)(psrc + j * 8);
            float4 a1 = *(const float4*)(psrc + j * 8 + 4);
            float av[8] = {a0.x, a0.y, a0.z, a0.w, a1.x, a1.y, a1.z, a1.w};
            uint32_t hw[4], lw[4];
            #pragma unroll
            for (int q = 0; q < 4; q++) {
                ssq = fmaf(av[2 * q], av[2 * q], ssq);
                ssq = fmaf(av[2 * q + 1], av[2 * q + 1], ssq);
                __nv_bfloat16 h0 = __float2bfloat16(av[2 * q]);
                __nv_bfloat16 h1 = __float2bfloat16(av[2 * q + 1]);
                __nv_bfloat162 hp(h0, h1);
                __nv_bfloat162 lp(__float2bfloat16(av[2 * q]     - __bfloat162float(h0)),
                                  __float2bfloat16(av[2 * q + 1] - __bfloat162float(h1)));
                hw[q] = *(uint32_t*)&hp;
                lw[q] = *(uint32_t*)&lp;
            }
            STS128U(ph + sts + j * 16, hw[0], hw[1], hw[2], hw[3]);
            STS128U(pl + sts + j * 16, lw[0], lw[1], lw[2], lw[3]);
        }
        red[r][tid & 3] = ssq;
    }
    __syncthreads();
    if (tid < 64) {
        float tot = red[tid][0] + red[tid][1] + red[tid][2] + red[tid][3];
        scl[tid] = 1.0f / fmaxf(sqrtf(tot), 1e-12f);
    }
    __syncthreads();

    // ---- mma mainloop: warp tile 16q x 32k ----
    const int wm = warp >> 1;       // 0..3
    const int wn = warp & 1;        // 0..1
    const uint32_t a_ld = (uint32_t)((wm * 16 + (lane & 15)) * SROWB + (lane >> 4) * 16);
    const uint32_t b_ld = (uint32_t)(((lane & 7) + ((lane >> 4) << 3) + wn * 32) * SROWB
                                     + ((lane >> 3) & 1) * 16);

    float c[4][4];
    #pragma unroll
    for (int nt = 0; nt < 4; nt++)
        #pragma unroll
        for (int r = 0; r < 4; r++) c[nt][r] = 0.0f;

    #pragma unroll
    for (int ks = 0; ks < 8; ks++) {
        const uint32_t ko = ks * 32;
        uint32_t ah[4], al[4], bh[8], bl[8];
        LDSM_X4(ah, qh + a_ld + ko);
        LDSM_X4(al, ql + a_ld + ko);
        LDSM_X4(&bh[0], ph + b_ld + ko);
        LDSM_X4(&bh[4], ph + b_ld + ko + 16 * SROWB);
        LDSM_X4(&bl[0], pl + b_ld + ko);
        LDSM_X4(&bl[4], pl + b_ld + ko + 16 * SROWB);
        #pragma unroll
        for (int nt = 0; nt < 4; nt++) {
            MMA16816(c[nt], ah, bh[nt * 2], bh[nt * 2 + 1]);
            MMA16816(c[nt], ah, bl[nt * 2], bl[nt * 2 + 1]);
            MMA16816(c[nt], al, bh[nt * 2], bh[nt * 2 + 1]);
        }
    }

    // ---- epilogue: scale by cluster norm, max over valid cols ----
    const int g  = lane >> 2;
    const int tg = lane & 3;
    float mlo = -3.4e38f, mhi = -3.4e38f;
    #pragma unroll
    for (int nt = 0; nt < 4; nt++) {
        int lc = wn * 32 + nt * 8 + 2 * tg;
        float s0 = scl[lc], s1 = scl[lc + 1];
        if (k0 + lc < kb) {
            mlo = fmaxf(mlo, c[nt][0] * s0);
            mhi = fmaxf(mhi, c[nt][2] * s0);
        }
        if (k0 + lc + 1 < kb) {
            mlo = fmaxf(mlo, c[nt][1] * s1);
            mhi = fmaxf(mhi, c[nt][3] * s1);
        }
    }
    mlo = fmaxf(mlo, __shfl_xor_sync(0xffffffffu, mlo, 1));
    mlo = fmaxf(mlo, __shfl_xor_sync(0xffffffffu, mlo, 2));
    mhi = fmaxf(mhi, __shfl_xor_sync(0xffffffffu, mhi, 1));
    mhi = fmaxf(mhi, __shfl_xor_sync(0xffffffffu, mhi, 2));
    if (tg == 0) {
        atomicMax(&g_qmax[b * LQ_ + wm * 16 + g],     flipf(mlo));
        atomicMax(&g_qmax[b * LQ_ + wm * 16 + g + 8], flipf(mhi));
    }

    // ---- last block for this batch computes the final sum ----
    __syncthreads();
    __threadfence();
    if (tid == 0) {
        int ntiles = (kb + 63) >> 6;
        lastflag = (atomicAdd(&g_tile_cnt[b], 1) == ntiles - 1);
    }
    __syncthreads();
    if (lastflag) {
        if (tid < 64) {
            float v = unflipf(g_qmax[b * LQ_ + tid]) *
                      (float)q_mask[b * LQ_ + tid];
            #pragma unroll
            for (int o = 16; o; o >>= 1)
                v += __shfl_down_sync(0xffffffffu, v, o);
            if ((tid & 31) == 0) red[0][tid >> 5] = v;
        }
        __syncthreads();
        if (tid == 0) out[b] = red[0][0] + red[0][1];
    }
}

// ======================= launch =======================
extern "C" void kernel_launch(void* const* d_in, const int* in_sizes, int n_in,
                              void* d_out, int out_size) {
    const float* q_hidden = (const float*)d_in[0];
    const float* d_hidden = (const float*)d_in[1];
    const float* Wm       = (const float*)d_in[2];
    const float* bias     = (const float*)d_in[3];
    const int*   q_mask   = (const int*)  d_in[4];
    const int*   d_mask   = (const int*)  d_in[5];
    const int*   labels   = (const int*)  d_in[6];
    const int*   pf       = (const int*)  d_in[7];
    float*       out      = (float*)d_out;

    cudaFuncSetAttribute(encode_kernel,
                         cudaFuncAttributeMaxDynamicSharedMemorySize, SMEM_DYN);
    cudaFuncSetAttribute(score_kernel,
                         cudaFuncAttributeMaxDynamicSharedMemorySize, SC_SMEM);

    kb_kernel<<<B_, 256>>>(d_mask, pf);
    prep_kernel<<<NZ + 128 + 4, 256>>>(Wm);
    encode_kernel<<<QBLK + DBLK, 256, SMEM_DYN>>>(q_hidden, d_hidden, bias,
                                                  q_mask, d_mask, labels);
    dim3 sg(KPAD / 64, B_);
    score_kernel<<<sg, 256, SC_SMEM>>>(q_mask, out);
}